// round 13
// baseline (speedup 1.0000x reference)
#include <cuda_runtime.h>
#include <math.h>

#define BSZ 128
#define NN 2000
#define DD 256
#define HH 8
#define CN 8
#define CTX 64

#define MCHUNKS 16
#define MROWS 125

#define NSPLIT 8
#define CHUNK 250
#define PAD 260
#define PAD4 65

// ---------------- scratch ----------------
__device__ float g_pm[BSZ * MCHUNKS * DD];
__device__ float g_qproj[BSZ * HH * DD];
__device__ float g_qnk[BSZ * HH * CN];
__device__ float g_l[BSZ * NSPLIT * HH];
__device__ float g_accE[BSZ * NSPLIT * HH * DD];
__device__ float g_accNF[BSZ * NSPLIT * HH * CN];
__device__ float g_qlog[BSZ * DD];
__device__ float g_qlogn[BSZ * CN];
__device__ float g_logits[BSZ * NN];
__device__ int   g_maskpart[128];
__device__ int   g_maskmode;        // 0=uint8, 1=int32, 2=float32
__device__ int   g_lcnt[BSZ];       // zero-init; tail resets for graph replay

// ---------------- K1: partial sums over n for mean (+ fused mask scan) ----------------
__global__ void k_mean_partial(const float* __restrict__ enc,
                               const unsigned char* __restrict__ mask) {
    int s = blockIdx.x, b = blockIdx.y, tid = threadIdx.x;
    const float* p = enc + ((size_t)(b * NN + s * MROWS)) * DD + tid;
    float acc = 0.f;
#pragma unroll 8
    for (int j = 0; j < MROWS; j++) acc += p[(size_t)j * DD];
    g_pm[(b * MCHUNKS + s) * DD + tid] = acc;

    // mask dtype scan: 64 blocks cover the guaranteed-valid first 256000 bytes
    if (s == 0 && b < 64) {
        int big = 0, off = 0;
        int base = b * 4000;
        for (int i = base + tid; i < base + 4000; i += 256) {
            unsigned char v = mask[i];
            if (v > 1) big = 1;
            else if (v == 1 && (i & 3)) off = 1;
        }
        big = __syncthreads_or(big);
        off = __syncthreads_or(off);
        if (tid == 0) { g_maskpart[2 * b] = big; g_maskpart[2 * b + 1] = off; }
    }
}

// ---------------- K2: per-batch query construction + projections ----------------
__global__ void __launch_bounds__(256) k_setup(const float* __restrict__ shelf,
                        const float* __restrict__ ctx,
                        const float* __restrict__ Wk,
                        const float* __restrict__ Wq,
                        const float* __restrict__ Wc,
                        const float* __restrict__ Wg,
                        const float* __restrict__ Wn,
                        const int* __restrict__ curnode) {
    __shared__ __align__(16) float sMean[DD];
    __shared__ __align__(16) float sX[2 * DD];
    __shared__ __align__(16) float sCtx[CTX];
    __shared__ __align__(16) float sQ[DD];
    int b = blockIdx.x, t = threadIdx.x, w = t >> 5, lane = t & 31;
    int sub = lane & 7, rg = lane >> 3;

    // block 0 combines mask-scan partials into the mode
    if (b == 0) {
        int bigv = 0, offv = 0;
        if (t < 64) { bigv = g_maskpart[2 * t]; offv = g_maskpart[2 * t + 1]; }
        int big = __syncthreads_or(bigv);
        int off = __syncthreads_or(offv);
        if (t == 0) g_maskmode = big ? 2 : (off ? 0 : 1);
    }

    float m = 0.f;
#pragma unroll
    for (int s = 0; s < MCHUNKS; s++) m += g_pm[(b * MCHUNKS + s) * DD + t];
    sMean[t] = m * (1.0f / NN);

    int cn = curnode[b];
    sX[t] = shelf[((size_t)b * NN + cn) * DD + t];
    if (t < CTX) sCtx[t] = ctx[b * CTX + t];
    __syncthreads();

    // ---- cn GEMV: rows of Wc (256x64), 8-lane subgroup per row ----
#pragma unroll 2
    for (int p = 0; p < 8; p++) {
        int r = (p * 8 + w) * 4 + rg;
        const float4* wc = (const float4*)(Wc + r * CTX);
        float acc = 0.f;
#pragma unroll
        for (int k = 0; k < 2; k++) {
            float4 wv = wc[sub + 8 * k];
            float4 xv = *(const float4*)(sCtx + 4 * (sub + 8 * k));
            acc += wv.x * xv.x + wv.y * xv.y + wv.z * xv.z + wv.w * xv.w;
        }
        acc += __shfl_xor_sync(0xffffffffu, acc, 1);
        acc += __shfl_xor_sync(0xffffffffu, acc, 2);
        acc += __shfl_xor_sync(0xffffffffu, acc, 4);
        if (sub == 0) sX[DD + r] = acc;
    }
    __syncthreads();

    // ---- q GEMV: q[r] = Wq[r]·[cur,cn] + Wg[r]·mean ----
#pragma unroll 2
    for (int p = 0; p < 8; p++) {
        int r = (p * 8 + w) * 4 + rg;
        const float4* wq = (const float4*)(Wq + r * 2 * DD);
        const float4* wg = (const float4*)(Wg + r * DD);
        float acc = 0.f;
#pragma unroll
        for (int k = 0; k < 16; k++) {
            float4 wv = wq[sub + 8 * k];
            float4 xv = *(const float4*)(sX + 4 * (sub + 8 * k));
            acc += wv.x * xv.x + wv.y * xv.y + wv.z * xv.z + wv.w * xv.w;
        }
#pragma unroll
        for (int k = 0; k < 8; k++) {
            float4 wv = wg[sub + 8 * k];
            float4 xv = *(const float4*)(sMean + 4 * (sub + 8 * k));
            acc += wv.x * xv.x + wv.y * xv.y + wv.z * xv.z + wv.w * xv.w;
        }
        acc += __shfl_xor_sync(0xffffffffu, acc, 1);
        acc += __shfl_xor_sync(0xffffffffu, acc, 2);
        acc += __shfl_xor_sync(0xffffffffu, acc, 4);
        if (sub == 0) sQ[r] = acc;
    }
    __syncthreads();

    // ---- qproj / qnk (coalesced over t) ----
#pragma unroll
    for (int h = 0; h < HH; h++) {
        float a = 0.f;
#pragma unroll
        for (int i = 0; i < 32; i++) a += sQ[h * 32 + i] * Wk[(h * 32 + i) * DD + t];
        g_qproj[(b * HH + h) * DD + t] = a;
    }
    if (t < HH * CN) {
        int h = t >> 3, c = t & 7;
        float a = 0.f;
#pragma unroll
        for (int i = 0; i < 32; i++) a += sQ[h * 32 + i] * Wn[(h * 32 + i) * CN + c];
        g_qnk[b * HH * CN + t] = a;
    }
}

// ---------------- K3: tiled attention, register-prefetch pipelined ----------------
__global__ void __launch_bounds__(256) k_attn(const float* __restrict__ enc,
                                              const float* __restrict__ nfeat) {
    __shared__ __align__(16) float sQ[HH * PAD];
    __shared__ __align__(16) float sQn[HH * 9];
    __shared__ __align__(16) float sE[32 * PAD];
    __shared__ __align__(16) float sNF[32 * CN];
    __shared__ __align__(16) float sC[32 * HH];
    __shared__ float sLr[256];

    const int s = blockIdx.x, b = blockIdx.y;
    const int t = threadIdx.x;
    const int iS = t >> 3, sS = t & 7;
    const int hB = t >> 3, cB = t & 7;
    const int b0 = sS & 1, b1 = (sS >> 1) & 1, b2 = (sS >> 2) & 1;

    for (int idx = t; idx < HH * DD; idx += 256)
        sQ[(idx >> 8) * PAD + (idx & 255)] = g_qproj[b * HH * DD + idx];
    if (t < HH * CN) sQn[(t >> 3) * 9 + (t & 7)] = g_qnk[b * HH * CN + t];

    float aE[HH];
#pragma unroll
    for (int h = 0; h < HH; h++) aE[h] = 0.f;
    float lrun = 0.f, aNF = 0.f;

    const float SC = 0.1767766952966369f;
    const size_t rowbase = (size_t)(b * NN + s * CHUNK);
    const float4* encb = (const float4*)(enc + rowbase * DD);   // chunk base, 64 f4/row
    const float4* nfb  = (const float4*)(nfeat + rowbase * CN); // 2 f4/row

    // ---- prologue: prefetch tile 0 (always full 32 rows) ----
    float4 v[8];
    float4 nv = make_float4(0.f, 0.f, 0.f, 0.f);
#pragma unroll
    for (int r = 0; r < 8; r++) v[r] = encb[r * 256 + t];
    if (t < 64) nv = nfb[t];

    for (int k = 0; k < 8; k++) {
        const int T = (k == 7) ? (CHUNK - 224) : 32;   // 26 on last tile
        __syncthreads();   // previous tile's readers done with sE/sNF

        // ---- store prefetched tile to smem ----
#pragma unroll
        for (int r = 0; r < 8; r++) {
            int idx = r * 256 + t;
            if (idx < T * 64) {
                int n = idx >> 6, e = (idx & 63) << 2;
                *(float4*)(sE + n * PAD + e) = v[r];
            }
        }
        if (t < T * 2) *(float4*)(&sNF[t * 4]) = nv;

        // ---- issue prefetch for tile k+1 (latency hides under phases A/B) ----
        if (k < 7) {
            const int Tn = (k + 1 == 7) ? (CHUNK - 224) : 32;
            const float4* gn = encb + (k + 1) * 2048;
#pragma unroll
            for (int r = 0; r < 8; r++) {
                int idx = r * 256 + t;
                v[r] = (idx < Tn * 64) ? gn[idx] : make_float4(0.f, 0.f, 0.f, 0.f);
            }
            if (t < Tn * 2) nv = nfb[(k + 1) * 64 + t];
        }
        __syncthreads();

        // ---- phase A: thread = (node iS, slice sS); 8 head-partials ----
        float acc[HH];
#pragma unroll
        for (int h = 0; h < HH; h++) acc[h] = 0.f;
        {
            const float4* eR4 = (const float4*)sE + iS * PAD4;
            const float4* qB4 = (const float4*)sQ;
#pragma unroll
            for (int j = 0; j < 8; j++) {
                float4 e4 = eR4[sS + 8 * j];
#pragma unroll
                for (int h = 0; h < HH; h++) {
                    float4 q4 = qB4[h * PAD4 + sS + 8 * j];
                    acc[h] += e4.x * q4.x + e4.y * q4.y + e4.z * q4.z + e4.w * q4.w;
                }
            }
            float nfv = sNF[iS * CN + sS];
#pragma unroll
            for (int h = 0; h < HH; h++) acc[h] += sQn[h * 9 + sS] * nfv;
        }
        float c4[4], c2[2], cval;
#pragma unroll
        for (int kk = 0; kk < 4; kk++) {
            float mine  = b0 ? acc[2 * kk + 1] : acc[2 * kk];
            float yours = b0 ? acc[2 * kk]     : acc[2 * kk + 1];
            c4[kk] = mine + __shfl_xor_sync(0xffffffffu, yours, 1);
        }
#pragma unroll
        for (int kk = 0; kk < 2; kk++) {
            float mine  = b1 ? c4[2 * kk + 1] : c4[2 * kk];
            float yours = b1 ? c4[2 * kk]     : c4[2 * kk + 1];
            c2[kk] = mine + __shfl_xor_sync(0xffffffffu, yours, 2);
        }
        {
            float mine  = b2 ? c2[1] : c2[0];
            float yours = b2 ? c2[0] : c2[1];
            cval = (mine + __shfl_xor_sync(0xffffffffu, yours, 4)) * SC;
        }

        float p = (iS < T) ? __expf(cval) : 0.f;
        sC[t] = p;
        lrun += p;
        __syncthreads();

        // ---- phase B: accumulate aE (thread = column e = t) ----
        {
            const float* eCol = sE + t;
#pragma unroll 8
            for (int n = 0; n < T; n++) {
                float4 p0 = *(const float4*)(sC + n * HH);
                float4 p1 = *(const float4*)(sC + n * HH + 4);
                float ev = eCol[n * PAD];
                aE[0] += p0.x * ev; aE[1] += p0.y * ev;
                aE[2] += p0.z * ev; aE[3] += p0.w * ev;
                aE[4] += p1.x * ev; aE[5] += p1.y * ev;
                aE[6] += p1.z * ev; aE[7] += p1.w * ev;
            }
        }
        if (t < 64) {
            for (int n = 0; n < T; n++)
                aNF += sC[n * HH + hB] * sNF[n * CN + cB];
        }
    }

    __syncthreads();
    sLr[t] = lrun;
    __syncthreads();
    const int part = b * NSPLIT + s;
#pragma unroll
    for (int h = 0; h < HH; h++)
        g_accE[((size_t)part * HH + h) * DD + t] = aE[h];
    if (t < 64) g_accNF[part * 64 + t] = aNF;
    if (t < HH) {
        float L = 0.f;
#pragma unroll
        for (int i = 0; i < 32; i++) L += sLr[i * 8 + t];
        g_l[part * HH + t] = L;
    }
}

// ---------------- K4: combine partials + epilogue (512 threads) ----------------
__global__ void __launch_bounds__(512) k_combine(const float* __restrict__ Wv,
                          const float* __restrict__ Wout,
                          const float* __restrict__ Wk2,
                          const float* __restrict__ Wn) {
    __shared__ float sLinv[HH];
    __shared__ __align__(16) float sV[HH * DD];
    __shared__ __align__(16) float sNFc[HH * CN];
    __shared__ __align__(16) float sO[DD];
    __shared__ __align__(16) float sG[DD];
    int b = blockIdx.x, t = threadIdx.x;
    int sub = t & 7;

    if (t < HH) {
        float L = 0.f;
#pragma unroll
        for (int p = 0; p < NSPLIT; p++)
            L += g_l[(b * NSPLIT + p) * HH + t];
        sLinv[t] = 1.0f / L;
    }
    __syncthreads();

#pragma unroll
    for (int r = 0; r < 4; r++) {
        int idx = r * 512 + t;
        int h = idx >> 8;
        float a = 0.f;
#pragma unroll
        for (int p = 0; p < NSPLIT; p++)
            a += g_accE[(((size_t)(b * NSPLIT) + p) * HH * DD) + idx];
        sV[idx] = a * sLinv[h];
    }
    if (t < HH * CN) {
        int h = t >> 3;
        float a = 0.f;
#pragma unroll
        for (int p = 0; p < NSPLIT; p++)
            a += g_accNF[(b * NSPLIT + p) * (HH * CN) + t];
        sNFc[t] = a * sLinv[h];
    }
    __syncthreads();

#pragma unroll
    for (int p = 0; p < 4; p++) {
        int r = p * 64 + (t >> 3);
        int h = r >> 5;
        const float4* wv = (const float4*)(Wv + r * DD);
        const float4* xv = (const float4*)(sV + h * DD);
        float acc = Wn[(DD + r) * CN + sub] * sNFc[h * CN + sub];
#pragma unroll
        for (int k = 0; k < 8; k++) {
            float4 a4 = wv[sub + 8 * k];
            float4 b4 = xv[sub + 8 * k];
            acc += a4.x * b4.x + a4.y * b4.y + a4.z * b4.z + a4.w * b4.w;
        }
        acc += __shfl_xor_sync(0xffffffffu, acc, 1);
        acc += __shfl_xor_sync(0xffffffffu, acc, 2);
        acc += __shfl_xor_sync(0xffffffffu, acc, 4);
        if (sub == 0) sO[r] = acc;
    }
    __syncthreads();

#pragma unroll
    for (int p = 0; p < 4; p++) {
        int r = p * 64 + (t >> 3);
        const float4* wo = (const float4*)(Wout + r * DD);
        float acc = 0.f;
#pragma unroll
        for (int k = 0; k < 8; k++) {
            float4 a4 = wo[sub + 8 * k];
            float4 b4 = *(const float4*)(sO + 4 * (sub + 8 * k));
            acc += a4.x * b4.x + a4.y * b4.y + a4.z * b4.z + a4.w * b4.w;
        }
        acc += __shfl_xor_sync(0xffffffffu, acc, 1);
        acc += __shfl_xor_sync(0xffffffffu, acc, 2);
        acc += __shfl_xor_sync(0xffffffffu, acc, 4);
        if (sub == 0) sG[r] = acc;
    }
    __syncthreads();

    if (t < DD) {
        float q = 0.f;
#pragma unroll 8
        for (int d = 0; d < DD; d++) q += sG[d] * Wk2[d * DD + t];
        g_qlog[b * DD + t] = q;
    } else if (t < DD + CN) {
        int c = t - DD;
        float q = 0.f;
#pragma unroll 8
        for (int d = 0; d < DD; d++) q += sG[d] * Wn[(2 * DD + d) * CN + c];
        g_qlogn[b * CN + c] = q;
    }
}

// ---------------- K5: masked logits + (tail) softmax ----------------
__global__ void __launch_bounds__(256) k_logits_softmax(
        const float* __restrict__ enc, const float* __restrict__ nfeat,
        const unsigned char* __restrict__ mask, float* __restrict__ out) {
    __shared__ __align__(16) float sQl[DD];
    __shared__ float sQn2[CN];
    __shared__ __align__(16) float sL[NN];
    __shared__ float sRed[40];
    __shared__ int sLast;
    int s = blockIdx.x, b = blockIdx.y;
    int t = threadIdx.x, w = t >> 5, lane = t & 31;
    const int iS = t >> 3, sS = t & 7;
    int mode = g_maskmode;

    sQl[t] = g_qlog[b * DD + t];
    if (t < CN) sQn2[t] = g_qlogn[b * CN + t];
    __syncthreads();

    const float4* ql4 = (const float4*)sQl;
    const size_t rowbase = (size_t)(b * NN + s * CHUNK);

    for (int n0 = 0; n0 < CHUNK; n0 += 32) {
        const int T = (CHUNK - n0 < 32) ? (CHUNK - n0) : 32;
        const int n = n0 + iS;
        float acc = 0.f;
        if (iS < T) {
            const float4* er4 = (const float4*)(enc + (rowbase + n) * DD);
#pragma unroll
            for (int j = 0; j < 8; j++) {
                float4 e4 = er4[sS + 8 * j];
                float4 q4 = ql4[sS + 8 * j];
                acc += e4.x * q4.x + e4.y * q4.y + e4.z * q4.z + e4.w * q4.w;
            }
            acc += sQn2[sS] * nfeat[(rowbase + n) * CN + sS];
        }
        acc += __shfl_xor_sync(0xffffffffu, acc, 1);
        acc += __shfl_xor_sync(0xffffffffu, acc, 2);
        acc += __shfl_xor_sync(0xffffffffu, acc, 4);
        if (sS == 0 && iS < T) {
            size_t idx = rowbase + n;
            bool mk;
            if (mode == 2)      mk = ((const float*)mask)[idx] != 0.0f;
            else if (mode == 1) mk = ((const int*)mask)[idx] != 0;
            else                mk = mask[idx] != 0;
            float lg = tanhf(acc * (1.0f / 16.0f)) * 10.0f;
            g_logits[idx] = mk ? -INFINITY : lg;
        }
    }

    // ---- softmax tail (8th block of batch b) ----
    __threadfence();
    __syncthreads();
    if (t == 0) sLast = (atomicAdd(&g_lcnt[b], 1) == NSPLIT - 1) ? 1 : 0;
    __syncthreads();
    if (!sLast) return;
    __threadfence();

    const float4* src = (const float4*)(g_logits + (size_t)b * NN);
    for (int i = t; i < NN / 4; i += 256) {
        float4 v = src[i];
        *(float4*)(sL + i * 4) = v;
    }
    __syncthreads();

    float mx = -INFINITY;
    for (int n = t; n < NN; n += 256) mx = fmaxf(mx, sL[n]);
#pragma unroll
    for (int o = 16; o > 0; o >>= 1) mx = fmaxf(mx, __shfl_xor_sync(0xffffffffu, mx, o));
    if (lane == 0) sRed[w] = mx;
    __syncthreads();
    if (t == 0) {
        float m2 = -INFINITY;
#pragma unroll
        for (int i = 0; i < 8; i++) m2 = fmaxf(m2, sRed[i]);
        sRed[32] = m2;
    }
    __syncthreads();
    float M = sRed[32];

    float sm = 0.f;
    for (int n = t; n < NN; n += 256) sm += __expf(sL[n] - M);
#pragma unroll
    for (int o = 16; o > 0; o >>= 1) sm += __shfl_xor_sync(0xffffffffu, sm, o);
    if (lane == 0) sRed[8 + w] = sm;
    __syncthreads();
    if (t == 0) {
        float s2 = 0.f;
#pragma unroll
        for (int i = 0; i < 8; i++) s2 += sRed[8 + i];
        sRed[33] = 1.0f / s2;
    }
    __syncthreads();
    float inv = sRed[33];
    for (int n = t; n < NN; n += 256)
        out[(size_t)b * NN + n] = __expf(sL[n] - M) * inv;
    if (t == 0) g_lcnt[b] = 0;
}

// ---------------- launch ----------------
extern "C" void kernel_launch(void* const* d_in, const int* in_sizes, int n_in,
                              void* d_out, int out_size) {
    const float* shelf = (const float*)d_in[0];
    const float* enc   = (const float*)d_in[1];
    const float* ctx   = (const float*)d_in[2];
    const float* nfeat = (const float*)d_in[3];
    const float* Wk    = (const float*)d_in[4];
    const float* Wv    = (const float*)d_in[5];
    const float* Wk2   = (const float*)d_in[6];
    const float* Wq    = (const float*)d_in[7];
    const float* Wout  = (const float*)d_in[8];
    const float* Wc    = (const float*)d_in[9];
    const float* Wg    = (const float*)d_in[10];
    const float* Wn    = (const float*)d_in[11];
    const int*   cur   = (const int*)d_in[12];
    const unsigned char* mask = (const unsigned char*)d_in[13];
    float* out = (float*)d_out;

    k_mean_partial<<<dim3(MCHUNKS, BSZ), 256>>>(enc, mask);
    k_setup<<<BSZ, 256>>>(shelf, ctx, Wk, Wq, Wc, Wg, Wn, cur);
    k_attn<<<dim3(NSPLIT, BSZ), 256>>>(enc, nfeat);
    k_combine<<<BSZ, 512>>>(Wv, Wout, Wk2, Wn);
    k_logits_softmax<<<dim3(NSPLIT, BSZ), 256>>>(enc, nfeat, mask, out);
}

// round 14
// speedup vs baseline: 1.3939x; 1.3939x over previous
#include <cuda_runtime.h>
#include <math.h>

#define BSZ 128
#define NN 2000
#define DD 256
#define HH 8
#define CN 8
#define CTX 64

#define MCHUNKS 16
#define MROWS 125

#define NSPLIT 8
#define CHUNK 250
#define PAD 260
#define PAD4 65

typedef unsigned long long u64;

__device__ __forceinline__ u64 ffma2(u64 a, u64 b, u64 c) {
    u64 d;
    asm("fma.rn.f32x2 %0, %1, %2, %3;" : "=l"(d) : "l"(a), "l"(b), "l"(c));
    return d;
}
__device__ __forceinline__ u64 pack2(float lo, float hi) {
    u64 v;
    asm("mov.b64 %0, {%1, %2};" : "=l"(v) : "f"(lo), "f"(hi));
    return v;
}
__device__ __forceinline__ void unpack2(u64 v, float& lo, float& hi) {
    asm("mov.b64 {%0, %1}, %2;" : "=f"(lo), "=f"(hi) : "l"(v));
}

// ---------------- scratch ----------------
__device__ float g_pm[BSZ * MCHUNKS * DD];
__device__ float g_qproj[BSZ * HH * DD];
__device__ float g_qnk[BSZ * HH * CN];
__device__ float g_l[BSZ * NSPLIT * HH];
__device__ float g_accE[BSZ * NSPLIT * HH * DD];
__device__ float g_accNF[BSZ * NSPLIT * HH * CN];
__device__ float g_qlog[BSZ * DD];
__device__ float g_qlogn[BSZ * CN];
__device__ float g_logits[BSZ * NN];
__device__ int   g_maskpart[128];
__device__ int   g_maskmode;        // 0=uint8, 1=int32, 2=float32
__device__ int   g_lcnt[BSZ];       // zero-init; tail resets for graph replay

// ---------------- K1: partial sums over n for mean (+ fused mask scan) ----------------
__global__ void k_mean_partial(const float* __restrict__ enc,
                               const unsigned char* __restrict__ mask) {
    int s = blockIdx.x, b = blockIdx.y, tid = threadIdx.x;
    const float* p = enc + ((size_t)(b * NN + s * MROWS)) * DD + tid;
    float acc = 0.f;
#pragma unroll 8
    for (int j = 0; j < MROWS; j++) acc += p[(size_t)j * DD];
    g_pm[(b * MCHUNKS + s) * DD + tid] = acc;

    // mask dtype scan: 64 blocks cover the guaranteed-valid first 256000 bytes
    if (s == 0 && b < 64) {
        int big = 0, off = 0;
        int base = b * 4000;
        for (int i = base + tid; i < base + 4000; i += 256) {
            unsigned char v = mask[i];
            if (v > 1) big = 1;
            else if (v == 1 && (i & 3)) off = 1;
        }
        big = __syncthreads_or(big);
        off = __syncthreads_or(off);
        if (tid == 0) { g_maskpart[2 * b] = big; g_maskpart[2 * b + 1] = off; }
    }
}

// ---------------- K2: per-batch query construction + projections ----------------
__global__ void __launch_bounds__(256) k_setup(const float* __restrict__ shelf,
                        const float* __restrict__ ctx,
                        const float* __restrict__ Wk,
                        const float* __restrict__ Wq,
                        const float* __restrict__ Wc,
                        const float* __restrict__ Wg,
                        const float* __restrict__ Wn,
                        const int* __restrict__ curnode) {
    __shared__ __align__(16) float sMean[DD];
    __shared__ __align__(16) float sX[2 * DD];
    __shared__ __align__(16) float sCtx[CTX];
    __shared__ __align__(16) float sQ[DD];
    int b = blockIdx.x, t = threadIdx.x, w = t >> 5, lane = t & 31;
    int sub = lane & 7, rg = lane >> 3;

    // block 0 combines mask-scan partials into the mode
    if (b == 0) {
        int bigv = 0, offv = 0;
        if (t < 64) { bigv = g_maskpart[2 * t]; offv = g_maskpart[2 * t + 1]; }
        int big = __syncthreads_or(bigv);
        int off = __syncthreads_or(offv);
        if (t == 0) g_maskmode = big ? 2 : (off ? 0 : 1);
    }

    float m = 0.f;
#pragma unroll
    for (int s = 0; s < MCHUNKS; s++) m += g_pm[(b * MCHUNKS + s) * DD + t];
    sMean[t] = m * (1.0f / NN);

    int cn = curnode[b];
    sX[t] = shelf[((size_t)b * NN + cn) * DD + t];
    if (t < CTX) sCtx[t] = ctx[b * CTX + t];
    __syncthreads();

    // ---- cn GEMV: rows of Wc (256x64), 8-lane subgroup per row ----
#pragma unroll 2
    for (int p = 0; p < 8; p++) {
        int r = (p * 8 + w) * 4 + rg;
        const float4* wc = (const float4*)(Wc + r * CTX);
        float acc = 0.f;
#pragma unroll
        for (int k = 0; k < 2; k++) {
            float4 wv = wc[sub + 8 * k];
            float4 xv = *(const float4*)(sCtx + 4 * (sub + 8 * k));
            acc += wv.x * xv.x + wv.y * xv.y + wv.z * xv.z + wv.w * xv.w;
        }
        acc += __shfl_xor_sync(0xffffffffu, acc, 1);
        acc += __shfl_xor_sync(0xffffffffu, acc, 2);
        acc += __shfl_xor_sync(0xffffffffu, acc, 4);
        if (sub == 0) sX[DD + r] = acc;
    }
    __syncthreads();

    // ---- q GEMV: q[r] = Wq[r]·[cur,cn] + Wg[r]·mean ----
#pragma unroll 2
    for (int p = 0; p < 8; p++) {
        int r = (p * 8 + w) * 4 + rg;
        const float4* wq = (const float4*)(Wq + r * 2 * DD);
        const float4* wg = (const float4*)(Wg + r * DD);
        float acc = 0.f;
#pragma unroll
        for (int k = 0; k < 16; k++) {
            float4 wv = wq[sub + 8 * k];
            float4 xv = *(const float4*)(sX + 4 * (sub + 8 * k));
            acc += wv.x * xv.x + wv.y * xv.y + wv.z * xv.z + wv.w * xv.w;
        }
#pragma unroll
        for (int k = 0; k < 8; k++) {
            float4 wv = wg[sub + 8 * k];
            float4 xv = *(const float4*)(sMean + 4 * (sub + 8 * k));
            acc += wv.x * xv.x + wv.y * xv.y + wv.z * xv.z + wv.w * xv.w;
        }
        acc += __shfl_xor_sync(0xffffffffu, acc, 1);
        acc += __shfl_xor_sync(0xffffffffu, acc, 2);
        acc += __shfl_xor_sync(0xffffffffu, acc, 4);
        if (sub == 0) sQ[r] = acc;
    }
    __syncthreads();

    // ---- qproj / qnk (coalesced over t) ----
#pragma unroll
    for (int h = 0; h < HH; h++) {
        float a = 0.f;
#pragma unroll
        for (int i = 0; i < 32; i++) a += sQ[h * 32 + i] * Wk[(h * 32 + i) * DD + t];
        g_qproj[(b * HH + h) * DD + t] = a;
    }
    if (t < HH * CN) {
        int h = t >> 3, c = t & 7;
        float a = 0.f;
#pragma unroll
        for (int i = 0; i < 32; i++) a += sQ[h * 32 + i] * Wn[(h * 32 + i) * CN + c];
        g_qnk[b * HH * CN + t] = a;
    }
}

// ---------------- K3: tiled attention, f32x2 packed FMA ----------------
__global__ void __launch_bounds__(256) k_attn(const float* __restrict__ enc,
                                              const float* __restrict__ nfeat) {
    __shared__ __align__(16) float sQ[HH * PAD];
    __shared__ __align__(16) float sQn[HH * 9];
    __shared__ __align__(16) float sE[32 * PAD];
    __shared__ __align__(16) float sNF[32 * CN];
    __shared__ __align__(16) float sC[32 * HH];
    __shared__ float sLr[256];

    const int s = blockIdx.x, b = blockIdx.y;
    const int t = threadIdx.x;
    const int iS = t >> 3, sS = t & 7;
    const int hB = t >> 3, cB = t & 7;
    const int b0 = sS & 1, b1 = (sS >> 1) & 1, b2 = (sS >> 2) & 1;

    for (int idx = t; idx < HH * DD; idx += 256)
        sQ[(idx >> 8) * PAD + (idx & 255)] = g_qproj[b * HH * DD + idx];
    if (t < HH * CN) sQn[(t >> 3) * 9 + (t & 7)] = g_qnk[b * HH * CN + t];

    u64 aE2[4];
#pragma unroll
    for (int h = 0; h < 4; h++) aE2[h] = 0ull;
    float lrun = 0.f, aNF = 0.f;

    const float SC = 0.1767766952966369f;
    const size_t rowbase = (size_t)(b * NN + s * CHUNK);

    for (int k = 0; k < 8; k++) {
        const int n0 = k * 32;
        const int T = (k == 7) ? (CHUNK - 224) : 32;
        __syncthreads();

        const float4* gsrc = (const float4*)(enc + (rowbase + n0) * DD);
        const int nf4 = T * 64;
#pragma unroll
        for (int r = 0; r < 8; r++) {
            int idx = r * 256 + t;
            if (idx < nf4) {
                float4 v = gsrc[idx];
                int n = idx >> 6, e = (idx & 63) << 2;
                *(float4*)(sE + n * PAD + e) = v;
            }
        }
        if (t < T * 2) {
            float4 v = ((const float4*)(nfeat + (rowbase + n0) * CN))[t];
            *(float4*)(&sNF[t * 4]) = v;
        }
        __syncthreads();

        // ---- phase A: packed f32x2 dot products ----
        u64 acc2[HH];
#pragma unroll
        for (int h = 0; h < HH; h++) acc2[h] = 0ull;
        {
            const ulonglong2* eR2 = (const ulonglong2*)sE + iS * PAD4;
            const ulonglong2* qB2 = (const ulonglong2*)sQ;
#pragma unroll
            for (int j = 0; j < 8; j++) {
                ulonglong2 e2 = eR2[sS + 8 * j];
#pragma unroll
                for (int h = 0; h < HH; h++) {
                    ulonglong2 q2 = qB2[h * PAD4 + sS + 8 * j];
                    acc2[h] = ffma2(e2.x, q2.x, acc2[h]);
                    acc2[h] = ffma2(e2.y, q2.y, acc2[h]);
                }
            }
        }
        float acc[HH];
        {
            float nfv = sNF[iS * CN + sS];
#pragma unroll
            for (int h = 0; h < HH; h++) {
                float lo, hi;
                unpack2(acc2[h], lo, hi);
                acc[h] = lo + hi + sQn[h * 9 + sS] * nfv;
            }
        }
        // butterfly: reduce over slices while distributing heads
        float c4[4], c2[2], cval;
#pragma unroll
        for (int kk = 0; kk < 4; kk++) {
            float mine  = b0 ? acc[2 * kk + 1] : acc[2 * kk];
            float yours = b0 ? acc[2 * kk]     : acc[2 * kk + 1];
            c4[kk] = mine + __shfl_xor_sync(0xffffffffu, yours, 1);
        }
#pragma unroll
        for (int kk = 0; kk < 2; kk++) {
            float mine  = b1 ? c4[2 * kk + 1] : c4[2 * kk];
            float yours = b1 ? c4[2 * kk]     : c4[2 * kk + 1];
            c2[kk] = mine + __shfl_xor_sync(0xffffffffu, yours, 2);
        }
        {
            float mine  = b2 ? c2[1] : c2[0];
            float yours = b2 ? c2[0] : c2[1];
            cval = (mine + __shfl_xor_sync(0xffffffffu, yours, 4)) * SC;
        }

        float p = (iS < T) ? __expf(cval) : 0.f;
        sC[t] = p;
        lrun += p;
        __syncthreads();

        // ---- phase B: packed f32x2 accumulate (thread = column e = t) ----
        {
            const float* eCol = sE + t;
            const ulonglong2* pC = (const ulonglong2*)sC;
#pragma unroll 8
            for (int n = 0; n < T; n++) {
                ulonglong2 pa = pC[2 * n];       // heads (0,1),(2,3)
                ulonglong2 pb = pC[2 * n + 1];   // heads (4,5),(6,7)
                float ev = eCol[n * PAD];
                u64 ev2 = pack2(ev, ev);
                aE2[0] = ffma2(pa.x, ev2, aE2[0]);
                aE2[1] = ffma2(pa.y, ev2, aE2[1]);
                aE2[2] = ffma2(pb.x, ev2, aE2[2]);
                aE2[3] = ffma2(pb.y, ev2, aE2[3]);
            }
        }
        if (t < 64) {
            for (int n = 0; n < T; n++)
                aNF += sC[n * HH + hB] * sNF[n * CN + cB];
        }
    }

    __syncthreads();
    sLr[t] = lrun;
    __syncthreads();
    const int part = b * NSPLIT + s;
    {
        float aE[HH];
#pragma unroll
        for (int h = 0; h < 4; h++)
            unpack2(aE2[h], aE[2 * h], aE[2 * h + 1]);
#pragma unroll
        for (int h = 0; h < HH; h++)
            g_accE[((size_t)part * HH + h) * DD + t] = aE[h];
    }
    if (t < 64) g_accNF[part * 64 + t] = aNF;
    if (t < HH) {
        float L = 0.f;
#pragma unroll
        for (int i = 0; i < 32; i++) L += sLr[i * 8 + t];
        g_l[part * HH + t] = L;
    }
}

// ---------------- K4: combine partials + epilogue (512 threads) ----------------
__global__ void __launch_bounds__(512) k_combine(const float* __restrict__ Wv,
                          const float* __restrict__ Wout,
                          const float* __restrict__ Wk2,
                          const float* __restrict__ Wn) {
    __shared__ float sLinv[HH];
    __shared__ __align__(16) float sV[HH * DD];
    __shared__ __align__(16) float sNFc[HH * CN];
    __shared__ __align__(16) float sO[DD];
    __shared__ __align__(16) float sG[DD];
    int b = blockIdx.x, t = threadIdx.x;
    int sub = t & 7;

    if (t < HH) {
        float L = 0.f;
#pragma unroll
        for (int p = 0; p < NSPLIT; p++)
            L += g_l[(b * NSPLIT + p) * HH + t];
        sLinv[t] = 1.0f / L;
    }
    __syncthreads();

#pragma unroll
    for (int r = 0; r < 4; r++) {
        int idx = r * 512 + t;
        int h = idx >> 8;
        float a = 0.f;
#pragma unroll
        for (int p = 0; p < NSPLIT; p++)
            a += g_accE[(((size_t)(b * NSPLIT) + p) * HH * DD) + idx];
        sV[idx] = a * sLinv[h];
    }
    if (t < HH * CN) {
        int h = t >> 3;
        float a = 0.f;
#pragma unroll
        for (int p = 0; p < NSPLIT; p++)
            a += g_accNF[(b * NSPLIT + p) * (HH * CN) + t];
        sNFc[t] = a * sLinv[h];
    }
    __syncthreads();

#pragma unroll
    for (int p = 0; p < 4; p++) {
        int r = p * 64 + (t >> 3);
        int h = r >> 5;
        const float4* wv = (const float4*)(Wv + r * DD);
        const float4* xv = (const float4*)(sV + h * DD);
        float acc = Wn[(DD + r) * CN + sub] * sNFc[h * CN + sub];
#pragma unroll
        for (int k = 0; k < 8; k++) {
            float4 a4 = wv[sub + 8 * k];
            float4 b4 = xv[sub + 8 * k];
            acc += a4.x * b4.x + a4.y * b4.y + a4.z * b4.z + a4.w * b4.w;
        }
        acc += __shfl_xor_sync(0xffffffffu, acc, 1);
        acc += __shfl_xor_sync(0xffffffffu, acc, 2);
        acc += __shfl_xor_sync(0xffffffffu, acc, 4);
        if (sub == 0) sO[r] = acc;
    }
    __syncthreads();

#pragma unroll
    for (int p = 0; p < 4; p++) {
        int r = p * 64 + (t >> 3);
        const float4* wo = (const float4*)(Wout + r * DD);
        float acc = 0.f;
#pragma unroll
        for (int k = 0; k < 8; k++) {
            float4 a4 = wo[sub + 8 * k];
            float4 b4 = *(const float4*)(sO + 4 * (sub + 8 * k));
            acc += a4.x * b4.x + a4.y * b4.y + a4.z * b4.z + a4.w * b4.w;
        }
        acc += __shfl_xor_sync(0xffffffffu, acc, 1);
        acc += __shfl_xor_sync(0xffffffffu, acc, 2);
        acc += __shfl_xor_sync(0xffffffffu, acc, 4);
        if (sub == 0) sG[r] = acc;
    }
    __syncthreads();

    if (t < DD) {
        float q = 0.f;
#pragma unroll 8
        for (int d = 0; d < DD; d++) q += sG[d] * Wk2[d * DD + t];
        g_qlog[b * DD + t] = q;
    } else if (t < DD + CN) {
        int c = t - DD;
        float q = 0.f;
#pragma unroll 8
        for (int d = 0; d < DD; d++) q += sG[d] * Wn[(2 * DD + d) * CN + c];
        g_qlogn[b * CN + c] = q;
    }
}

// ---------------- K5: masked logits + (tail) softmax ----------------
__global__ void __launch_bounds__(256) k_logits_softmax(
        const float* __restrict__ enc, const float* __restrict__ nfeat,
        const unsigned char* __restrict__ mask, float* __restrict__ out) {
    __shared__ __align__(16) float sQl[DD];
    __shared__ float sQn2[CN];
    __shared__ __align__(16) float sL[NN];
    __shared__ float sRed[40];
    __shared__ int sLast;
    int s = blockIdx.x, b = blockIdx.y;
    int t = threadIdx.x, w = t >> 5, lane = t & 31;
    const int iS = t >> 3, sS = t & 7;
    int mode = g_maskmode;

    sQl[t] = g_qlog[b * DD + t];
    if (t < CN) sQn2[t] = g_qlogn[b * CN + t];
    __syncthreads();

    const float4* ql4 = (const float4*)sQl;
    const size_t rowbase = (size_t)(b * NN + s * CHUNK);

    for (int n0 = 0; n0 < CHUNK; n0 += 32) {
        const int T = (CHUNK - n0 < 32) ? (CHUNK - n0) : 32;
        const int n = n0 + iS;
        float acc = 0.f;
        if (iS < T) {
            const float4* er4 = (const float4*)(enc + (rowbase + n) * DD);
#pragma unroll
            for (int j = 0; j < 8; j++) {
                float4 e4 = er4[sS + 8 * j];
                float4 q4 = ql4[sS + 8 * j];
                acc += e4.x * q4.x + e4.y * q4.y + e4.z * q4.z + e4.w * q4.w;
            }
            acc += sQn2[sS] * nfeat[(rowbase + n) * CN + sS];
        }
        acc += __shfl_xor_sync(0xffffffffu, acc, 1);
        acc += __shfl_xor_sync(0xffffffffu, acc, 2);
        acc += __shfl_xor_sync(0xffffffffu, acc, 4);
        if (sS == 0 && iS < T) {
            size_t idx = rowbase + n;
            bool mk;
            if (mode == 2)      mk = ((const float*)mask)[idx] != 0.0f;
            else if (mode == 1) mk = ((const int*)mask)[idx] != 0;
            else                mk = mask[idx] != 0;
            float lg = tanhf(acc * (1.0f / 16.0f)) * 10.0f;
            g_logits[idx] = mk ? -INFINITY : lg;
        }
    }

    // ---- softmax tail (8th block of batch b) ----
    __threadfence();
    __syncthreads();
    if (t == 0) sLast = (atomicAdd(&g_lcnt[b], 1) == NSPLIT - 1) ? 1 : 0;
    __syncthreads();
    if (!sLast) return;
    __threadfence();

    const float4* src = (const float4*)(g_logits + (size_t)b * NN);
    for (int i = t; i < NN / 4; i += 256) {
        float4 v = src[i];
        *(float4*)(sL + i * 4) = v;
    }
    __syncthreads();

    float mx = -INFINITY;
    for (int n = t; n < NN; n += 256) mx = fmaxf(mx, sL[n]);
#pragma unroll
    for (int o = 16; o > 0; o >>= 1) mx = fmaxf(mx, __shfl_xor_sync(0xffffffffu, mx, o));
    if (lane == 0) sRed[w] = mx;
    __syncthreads();
    if (t == 0) {
        float m2 = -INFINITY;
#pragma unroll
        for (int i = 0; i < 8; i++) m2 = fmaxf(m2, sRed[i]);
        sRed[32] = m2;
    }
    __syncthreads();
    float M = sRed[32];

    float sm = 0.f;
    for (int n = t; n < NN; n += 256) sm += __expf(sL[n] - M);
#pragma unroll
    for (int o = 16; o > 0; o >>= 1) sm += __shfl_xor_sync(0xffffffffu, sm, o);
    if (lane == 0) sRed[8 + w] = sm;
    __syncthreads();
    if (t == 0) {
        float s2 = 0.f;
#pragma unroll
        for (int i = 0; i < 8; i++) s2 += sRed[8 + i];
        sRed[33] = 1.0f / s2;
    }
    __syncthreads();
    float inv = sRed[33];
    for (int n = t; n < NN; n += 256)
        out[(size_t)b * NN + n] = __expf(sL[n] - M) * inv;
    if (t == 0) g_lcnt[b] = 0;
}

// ---------------- launch ----------------
extern "C" void kernel_launch(void* const* d_in, const int* in_sizes, int n_in,
                              void* d_out, int out_size) {
    const float* shelf = (const float*)d_in[0];
    const float* enc   = (const float*)d_in[1];
    const float* ctx   = (const float*)d_in[2];
    const float* nfeat = (const float*)d_in[3];
    const float* Wk    = (const float*)d_in[4];
    const float* Wv    = (const float*)d_in[5];
    const float* Wk2   = (const float*)d_in[6];
    const float* Wq    = (const float*)d_in[7];
    const float* Wout  = (const float*)d_in[8];
    const float* Wc    = (const float*)d_in[9];
    const float* Wg    = (const float*)d_in[10];
    const float* Wn    = (const float*)d_in[11];
    const int*   cur   = (const int*)d_in[12];
    const unsigned char* mask = (const unsigned char*)d_in[13];
    float* out = (float*)d_out;

    k_mean_partial<<<dim3(MCHUNKS, BSZ), 256>>>(enc, mask);
    k_setup<<<BSZ, 256>>>(shelf, ctx, Wk, Wq, Wc, Wg, Wn, cur);
    k_attn<<<dim3(NSPLIT, BSZ), 256>>>(enc, nfeat);
    k_combine<<<BSZ, 512>>>(Wv, Wout, Wk2, Wn);
    k_logits_softmax<<<dim3(NSPLIT, BSZ), 256>>>(enc, nfeat, mask, out);
}

// round 15
// speedup vs baseline: 1.4133x; 1.0139x over previous
#include <cuda_runtime.h>
#include <math.h>

#define BSZ 128
#define NN 2000
#define DD 256
#define HH 8
#define CN 8
#define CTX 64

#define MCHUNKS 16
#define MROWS 125

#define NSPLIT 8
#define CHUNK 250
#define PAD 260
#define PAD4 65

typedef unsigned long long u64;

__device__ __forceinline__ u64 ffma2(u64 a, u64 b, u64 c) {
    u64 d;
    asm("fma.rn.f32x2 %0, %1, %2, %3;" : "=l"(d) : "l"(a), "l"(b), "l"(c));
    return d;
}
__device__ __forceinline__ u64 pack2(float lo, float hi) {
    u64 v;
    asm("mov.b64 %0, {%1, %2};" : "=l"(v) : "f"(lo), "f"(hi));
    return v;
}
__device__ __forceinline__ void unpack2(u64 v, float& lo, float& hi) {
    asm("mov.b64 {%0, %1}, %2;" : "=f"(lo), "=f"(hi) : "l"(v));
}

// ---------------- scratch ----------------
__device__ float g_pm[BSZ * MCHUNKS * DD];
__device__ float g_qproj[BSZ * HH * DD];
__device__ float g_qnk[BSZ * HH * CN];
__device__ float g_l[BSZ * NSPLIT * HH];
__device__ float g_accE[BSZ * NSPLIT * HH * DD];
__device__ float g_accNF[BSZ * NSPLIT * HH * CN];
__device__ float g_qlog[BSZ * DD];
__device__ float g_qlogn[BSZ * CN];
__device__ float g_logits[BSZ * NN];
__device__ int   g_maskpart[128];
__device__ int   g_maskmode;        // 0=uint8, 1=int32, 2=float32
__device__ int   g_lcnt[BSZ];       // zero-init; tail resets for graph replay

// ---------------- K0: no-op (shifts ncu capture slot onto k_attn) ----------------
__global__ void k_nop() {}

// ---------------- K1: mean partials, float4 loads (+ fused mask scan) ----------------
__global__ void __launch_bounds__(256) k_mean_partial(const float* __restrict__ enc,
                               const unsigned char* __restrict__ mask) {
    __shared__ __align__(16) float4 sP[4][64];
    int s = blockIdx.x, b = blockIdx.y, t = threadIdx.x;
    int c4 = t & 63, rg = t >> 6;

    // rows [s*125, s*125+125), thread covers rows rg, rg+4, ... at float4 column c4
    const float4* p = (const float4*)(enc + ((size_t)(b * NN + s * MROWS)) * DD) + c4;
    float4 acc = make_float4(0.f, 0.f, 0.f, 0.f);
#pragma unroll 4
    for (int j = rg; j < MROWS; j += 4) {
        float4 v = p[(size_t)j * 64];
        acc.x += v.x; acc.y += v.y; acc.z += v.z; acc.w += v.w;
    }
    sP[rg][c4] = acc;
    __syncthreads();
    if (t < 64) {
        float4 a0 = sP[0][t], a1 = sP[1][t], a2 = sP[2][t], a3 = sP[3][t];
        float4 r;
        r.x = a0.x + a1.x + a2.x + a3.x;
        r.y = a0.y + a1.y + a2.y + a3.y;
        r.z = a0.z + a1.z + a2.z + a3.z;
        r.w = a0.w + a1.w + a2.w + a3.w;
        *(float4*)(g_pm + (b * MCHUNKS + s) * DD + t * 4) = r;
    }

    // mask dtype scan: 64 blocks cover the guaranteed-valid first 256000 bytes
    if (s == 0 && b < 64) {
        int big = 0, off = 0;
        int base = b * 4000;
        for (int i = base + t; i < base + 4000; i += 256) {
            unsigned char v = mask[i];
            if (v > 1) big = 1;
            else if (v == 1 && (i & 3)) off = 1;
        }
        big = __syncthreads_or(big);
        off = __syncthreads_or(off);
        if (t == 0) { g_maskpart[2 * b] = big; g_maskpart[2 * b + 1] = off; }
    }
}

// ---------------- K2: per-batch query construction + projections ----------------
__global__ void __launch_bounds__(256) k_setup(const float* __restrict__ shelf,
                        const float* __restrict__ ctx,
                        const float* __restrict__ Wk,
                        const float* __restrict__ Wq,
                        const float* __restrict__ Wc,
                        const float* __restrict__ Wg,
                        const float* __restrict__ Wn,
                        const int* __restrict__ curnode) {
    __shared__ __align__(16) float sMean[DD];
    __shared__ __align__(16) float sX[2 * DD];
    __shared__ __align__(16) float sCtx[CTX];
    __shared__ __align__(16) float sQ[DD];
    int b = blockIdx.x, t = threadIdx.x, w = t >> 5, lane = t & 31;
    int sub = lane & 7, rg = lane >> 3;

    // block 0 combines mask-scan partials into the mode
    if (b == 0) {
        int bigv = 0, offv = 0;
        if (t < 64) { bigv = g_maskpart[2 * t]; offv = g_maskpart[2 * t + 1]; }
        int big = __syncthreads_or(bigv);
        int off = __syncthreads_or(offv);
        if (t == 0) g_maskmode = big ? 2 : (off ? 0 : 1);
    }

    float m = 0.f;
#pragma unroll
    for (int s = 0; s < MCHUNKS; s++) m += g_pm[(b * MCHUNKS + s) * DD + t];
    sMean[t] = m * (1.0f / NN);

    int cn = curnode[b];
    sX[t] = shelf[((size_t)b * NN + cn) * DD + t];
    if (t < CTX) sCtx[t] = ctx[b * CTX + t];
    __syncthreads();

    // ---- cn GEMV: rows of Wc (256x64), 8-lane subgroup per row ----
#pragma unroll 2
    for (int p = 0; p < 8; p++) {
        int r = (p * 8 + w) * 4 + rg;
        const float4* wc = (const float4*)(Wc + r * CTX);
        float acc = 0.f;
#pragma unroll
        for (int k = 0; k < 2; k++) {
            float4 wv = wc[sub + 8 * k];
            float4 xv = *(const float4*)(sCtx + 4 * (sub + 8 * k));
            acc += wv.x * xv.x + wv.y * xv.y + wv.z * xv.z + wv.w * xv.w;
        }
        acc += __shfl_xor_sync(0xffffffffu, acc, 1);
        acc += __shfl_xor_sync(0xffffffffu, acc, 2);
        acc += __shfl_xor_sync(0xffffffffu, acc, 4);
        if (sub == 0) sX[DD + r] = acc;
    }
    __syncthreads();

    // ---- q GEMV: q[r] = Wq[r]·[cur,cn] + Wg[r]·mean ----
#pragma unroll 2
    for (int p = 0; p < 8; p++) {
        int r = (p * 8 + w) * 4 + rg;
        const float4* wq = (const float4*)(Wq + r * 2 * DD);
        const float4* wg = (const float4*)(Wg + r * DD);
        float acc = 0.f;
#pragma unroll
        for (int k = 0; k < 16; k++) {
            float4 wv = wq[sub + 8 * k];
            float4 xv = *(const float4*)(sX + 4 * (sub + 8 * k));
            acc += wv.x * xv.x + wv.y * xv.y + wv.z * xv.z + wv.w * xv.w;
        }
#pragma unroll
        for (int k = 0; k < 8; k++) {
            float4 wv = wg[sub + 8 * k];
            float4 xv = *(const float4*)(sMean + 4 * (sub + 8 * k));
            acc += wv.x * xv.x + wv.y * xv.y + wv.z * xv.z + wv.w * xv.w;
        }
        acc += __shfl_xor_sync(0xffffffffu, acc, 1);
        acc += __shfl_xor_sync(0xffffffffu, acc, 2);
        acc += __shfl_xor_sync(0xffffffffu, acc, 4);
        if (sub == 0) sQ[r] = acc;
    }
    __syncthreads();

    // ---- qproj / qnk (coalesced over t) ----
#pragma unroll
    for (int h = 0; h < HH; h++) {
        float a = 0.f;
#pragma unroll
        for (int i = 0; i < 32; i++) a += sQ[h * 32 + i] * Wk[(h * 32 + i) * DD + t];
        g_qproj[(b * HH + h) * DD + t] = a;
    }
    if (t < HH * CN) {
        int h = t >> 3, c = t & 7;
        float a = 0.f;
#pragma unroll
        for (int i = 0; i < 32; i++) a += sQ[h * 32 + i] * Wn[(h * 32 + i) * CN + c];
        g_qnk[b * HH * CN + t] = a;
    }
}

// ---------------- K3: tiled attention, f32x2 packed FMA ----------------
__global__ void __launch_bounds__(256) k_attn(const float* __restrict__ enc,
                                              const float* __restrict__ nfeat) {
    __shared__ __align__(16) float sQ[HH * PAD];
    __shared__ __align__(16) float sQn[HH * 9];
    __shared__ __align__(16) float sE[32 * PAD];
    __shared__ __align__(16) float sNF[32 * CN];
    __shared__ __align__(16) float sC[32 * HH];
    __shared__ float sLr[256];

    const int s = blockIdx.x, b = blockIdx.y;
    const int t = threadIdx.x;
    const int iS = t >> 3, sS = t & 7;
    const int hB = t >> 3, cB = t & 7;
    const int b0 = sS & 1, b1 = (sS >> 1) & 1, b2 = (sS >> 2) & 1;

    for (int idx = t; idx < HH * DD; idx += 256)
        sQ[(idx >> 8) * PAD + (idx & 255)] = g_qproj[b * HH * DD + idx];
    if (t < HH * CN) sQn[(t >> 3) * 9 + (t & 7)] = g_qnk[b * HH * CN + t];

    u64 aE2[4];
#pragma unroll
    for (int h = 0; h < 4; h++) aE2[h] = 0ull;
    float lrun = 0.f, aNF = 0.f;

    const float SC = 0.1767766952966369f;
    const size_t rowbase = (size_t)(b * NN + s * CHUNK);

    for (int k = 0; k < 8; k++) {
        const int n0 = k * 32;
        const int T = (k == 7) ? (CHUNK - 224) : 32;
        __syncthreads();

        const float4* gsrc = (const float4*)(enc + (rowbase + n0) * DD);
        const int nf4 = T * 64;
#pragma unroll
        for (int r = 0; r < 8; r++) {
            int idx = r * 256 + t;
            if (idx < nf4) {
                float4 v = gsrc[idx];
                int n = idx >> 6, e = (idx & 63) << 2;
                *(float4*)(sE + n * PAD + e) = v;
            }
        }
        if (t < T * 2) {
            float4 v = ((const float4*)(nfeat + (rowbase + n0) * CN))[t];
            *(float4*)(&sNF[t * 4]) = v;
        }
        __syncthreads();

        // ---- phase A: packed f32x2 dot products ----
        u64 acc2[HH];
#pragma unroll
        for (int h = 0; h < HH; h++) acc2[h] = 0ull;
        {
            const ulonglong2* eR2 = (const ulonglong2*)sE + iS * PAD4;
            const ulonglong2* qB2 = (const ulonglong2*)sQ;
#pragma unroll
            for (int j = 0; j < 8; j++) {
                ulonglong2 e2 = eR2[sS + 8 * j];
#pragma unroll
                for (int h = 0; h < HH; h++) {
                    ulonglong2 q2 = qB2[h * PAD4 + sS + 8 * j];
                    acc2[h] = ffma2(e2.x, q2.x, acc2[h]);
                    acc2[h] = ffma2(e2.y, q2.y, acc2[h]);
                }
            }
        }
        float acc[HH];
        {
            float nfv = sNF[iS * CN + sS];
#pragma unroll
            for (int h = 0; h < HH; h++) {
                float lo, hi;
                unpack2(acc2[h], lo, hi);
                acc[h] = lo + hi + sQn[h * 9 + sS] * nfv;
            }
        }
        // butterfly: reduce over slices while distributing heads
        float c4[4], c2[2], cval;
#pragma unroll
        for (int kk = 0; kk < 4; kk++) {
            float mine  = b0 ? acc[2 * kk + 1] : acc[2 * kk];
            float yours = b0 ? acc[2 * kk]     : acc[2 * kk + 1];
            c4[kk] = mine + __shfl_xor_sync(0xffffffffu, yours, 1);
        }
#pragma unroll
        for (int kk = 0; kk < 2; kk++) {
            float mine  = b1 ? c4[2 * kk + 1] : c4[2 * kk];
            float yours = b1 ? c4[2 * kk]     : c4[2 * kk + 1];
            c2[kk] = mine + __shfl_xor_sync(0xffffffffu, yours, 2);
        }
        {
            float mine  = b2 ? c2[1] : c2[0];
            float yours = b2 ? c2[0] : c2[1];
            cval = (mine + __shfl_xor_sync(0xffffffffu, yours, 4)) * SC;
        }

        float p = (iS < T) ? __expf(cval) : 0.f;
        sC[t] = p;
        lrun += p;
        __syncthreads();

        // ---- phase B: packed f32x2 accumulate (thread = column e = t) ----
        {
            const float* eCol = sE + t;
            const ulonglong2* pC = (const ulonglong2*)sC;
#pragma unroll 8
            for (int n = 0; n < T; n++) {
                ulonglong2 pa = pC[2 * n];
                ulonglong2 pb = pC[2 * n + 1];
                float ev = eCol[n * PAD];
                u64 ev2 = pack2(ev, ev);
                aE2[0] = ffma2(pa.x, ev2, aE2[0]);
                aE2[1] = ffma2(pa.y, ev2, aE2[1]);
                aE2[2] = ffma2(pb.x, ev2, aE2[2]);
                aE2[3] = ffma2(pb.y, ev2, aE2[3]);
            }
        }
        if (t < 64) {
            for (int n = 0; n < T; n++)
                aNF += sC[n * HH + hB] * sNF[n * CN + cB];
        }
    }

    __syncthreads();
    sLr[t] = lrun;
    __syncthreads();
    const int part = b * NSPLIT + s;
    {
        float aE[HH];
#pragma unroll
        for (int h = 0; h < 4; h++)
            unpack2(aE2[h], aE[2 * h], aE[2 * h + 1]);
#pragma unroll
        for (int h = 0; h < HH; h++)
            g_accE[((size_t)part * HH + h) * DD + t] = aE[h];
    }
    if (t < 64) g_accNF[part * 64 + t] = aNF;
    if (t < HH) {
        float L = 0.f;
#pragma unroll
        for (int i = 0; i < 32; i++) L += sLr[i * 8 + t];
        g_l[part * HH + t] = L;
    }
}

// ---------------- K4: combine partials + epilogue (512 threads) ----------------
__global__ void __launch_bounds__(512) k_combine(const float* __restrict__ Wv,
                          const float* __restrict__ Wout,
                          const float* __restrict__ Wk2,
                          const float* __restrict__ Wn) {
    __shared__ float sLinv[HH];
    __shared__ __align__(16) float sV[HH * DD];
    __shared__ __align__(16) float sNFc[HH * CN];
    __shared__ __align__(16) float sO[DD];
    __shared__ __align__(16) float sG[DD];
    int b = blockIdx.x, t = threadIdx.x;
    int sub = t & 7;

    if (t < HH) {
        float L = 0.f;
#pragma unroll
        for (int p = 0; p < NSPLIT; p++)
            L += g_l[(b * NSPLIT + p) * HH + t];
        sLinv[t] = 1.0f / L;
    }
    __syncthreads();

#pragma unroll
    for (int r = 0; r < 4; r++) {
        int idx = r * 512 + t;
        int h = idx >> 8;
        float a = 0.f;
#pragma unroll
        for (int p = 0; p < NSPLIT; p++)
            a += g_accE[(((size_t)(b * NSPLIT) + p) * HH * DD) + idx];
        sV[idx] = a * sLinv[h];
    }
    if (t < HH * CN) {
        int h = t >> 3;
        float a = 0.f;
#pragma unroll
        for (int p = 0; p < NSPLIT; p++)
            a += g_accNF[(b * NSPLIT + p) * (HH * CN) + t];
        sNFc[t] = a * sLinv[h];
    }
    __syncthreads();

#pragma unroll
    for (int p = 0; p < 4; p++) {
        int r = p * 64 + (t >> 3);
        int h = r >> 5;
        const float4* wv = (const float4*)(Wv + r * DD);
        const float4* xv = (const float4*)(sV + h * DD);
        float acc = Wn[(DD + r) * CN + sub] * sNFc[h * CN + sub];
#pragma unroll
        for (int k = 0; k < 8; k++) {
            float4 a4 = wv[sub + 8 * k];
            float4 b4 = xv[sub + 8 * k];
            acc += a4.x * b4.x + a4.y * b4.y + a4.z * b4.z + a4.w * b4.w;
        }
        acc += __shfl_xor_sync(0xffffffffu, acc, 1);
        acc += __shfl_xor_sync(0xffffffffu, acc, 2);
        acc += __shfl_xor_sync(0xffffffffu, acc, 4);
        if (sub == 0) sO[r] = acc;
    }
    __syncthreads();

#pragma unroll
    for (int p = 0; p < 4; p++) {
        int r = p * 64 + (t >> 3);
        const float4* wo = (const float4*)(Wout + r * DD);
        float acc = 0.f;
#pragma unroll
        for (int k = 0; k < 8; k++) {
            float4 a4 = wo[sub + 8 * k];
            float4 b4 = *(const float4*)(sO + 4 * (sub + 8 * k));
            acc += a4.x * b4.x + a4.y * b4.y + a4.z * b4.z + a4.w * b4.w;
        }
        acc += __shfl_xor_sync(0xffffffffu, acc, 1);
        acc += __shfl_xor_sync(0xffffffffu, acc, 2);
        acc += __shfl_xor_sync(0xffffffffu, acc, 4);
        if (sub == 0) sG[r] = acc;
    }
    __syncthreads();

    if (t < DD) {
        float q = 0.f;
#pragma unroll 8
        for (int d = 0; d < DD; d++) q += sG[d] * Wk2[d * DD + t];
        g_qlog[b * DD + t] = q;
    } else if (t < DD + CN) {
        int c = t - DD;
        float q = 0.f;
#pragma unroll 8
        for (int d = 0; d < DD; d++) q += sG[d] * Wn[(2 * DD + d) * CN + c];
        g_qlogn[b * CN + c] = q;
    }
}

// ---------------- K5: masked logits + (tail) softmax ----------------
__global__ void __launch_bounds__(256) k_logits_softmax(
        const float* __restrict__ enc, const float* __restrict__ nfeat,
        const unsigned char* __restrict__ mask, float* __restrict__ out) {
    __shared__ __align__(16) float sQl[DD];
    __shared__ float sQn2[CN];
    __shared__ __align__(16) float sL[NN];
    __shared__ float sRed[40];
    __shared__ int sLast;
    int s = blockIdx.x, b = blockIdx.y;
    int t = threadIdx.x, w = t >> 5, lane = t & 31;
    const int iS = t >> 3, sS = t & 7;
    int mode = g_maskmode;

    sQl[t] = g_qlog[b * DD + t];
    if (t < CN) sQn2[t] = g_qlogn[b * CN + t];
    __syncthreads();

    const float4* ql4 = (const float4*)sQl;
    const size_t rowbase = (size_t)(b * NN + s * CHUNK);

    for (int n0 = 0; n0 < CHUNK; n0 += 32) {
        const int T = (CHUNK - n0 < 32) ? (CHUNK - n0) : 32;
        const int n = n0 + iS;
        float acc = 0.f;
        if (iS < T) {
            const float4* er4 = (const float4*)(enc + (rowbase + n) * DD);
#pragma unroll
            for (int j = 0; j < 8; j++) {
                float4 e4 = er4[sS + 8 * j];
                float4 q4 = ql4[sS + 8 * j];
                acc += e4.x * q4.x + e4.y * q4.y + e4.z * q4.z + e4.w * q4.w;
            }
            acc += sQn2[sS] * nfeat[(rowbase + n) * CN + sS];
        }
        acc += __shfl_xor_sync(0xffffffffu, acc, 1);
        acc += __shfl_xor_sync(0xffffffffu, acc, 2);
        acc += __shfl_xor_sync(0xffffffffu, acc, 4);
        if (sS == 0 && iS < T) {
            size_t idx = rowbase + n;
            bool mk;
            if (mode == 2)      mk = ((const float*)mask)[idx] != 0.0f;
            else if (mode == 1) mk = ((const int*)mask)[idx] != 0;
            else                mk = mask[idx] != 0;
            float lg = tanhf(acc * (1.0f / 16.0f)) * 10.0f;
            g_logits[idx] = mk ? -INFINITY : lg;
        }
    }

    // ---- softmax tail (8th block of batch b) ----
    __threadfence();
    __syncthreads();
    if (t == 0) sLast = (atomicAdd(&g_lcnt[b], 1) == NSPLIT - 1) ? 1 : 0;
    __syncthreads();
    if (!sLast) return;
    __threadfence();

    const float4* src = (const float4*)(g_logits + (size_t)b * NN);
    for (int i = t; i < NN / 4; i += 256) {
        float4 v = src[i];
        *(float4*)(sL + i * 4) = v;
    }
    __syncthreads();

    float mx = -INFINITY;
    for (int n = t; n < NN; n += 256) mx = fmaxf(mx, sL[n]);
#pragma unroll
    for (int o = 16; o > 0; o >>= 1) mx = fmaxf(mx, __shfl_xor_sync(0xffffffffu, mx, o));
    if (lane == 0) sRed[w] = mx;
    __syncthreads();
    if (t == 0) {
        float m2 = -INFINITY;
#pragma unroll
        for (int i = 0; i < 8; i++) m2 = fmaxf(m2, sRed[i]);
        sRed[32] = m2;
    }
    __syncthreads();
    float M = sRed[32];

    float sm = 0.f;
    for (int n = t; n < NN; n += 256) sm += __expf(sL[n] - M);
#pragma unroll
    for (int o = 16; o > 0; o >>= 1) sm += __shfl_xor_sync(0xffffffffu, sm, o);
    if (lane == 0) sRed[8 + w] = sm;
    __syncthreads();
    if (t == 0) {
        float s2 = 0.f;
#pragma unroll
        for (int i = 0; i < 8; i++) s2 += sRed[8 + i];
        sRed[33] = 1.0f / s2;
    }
    __syncthreads();
    float inv = sRed[33];
    for (int n = t; n < NN; n += 256)
        out[(size_t)b * NN + n] = __expf(sL[n] - M) * inv;
    if (t == 0) g_lcnt[b] = 0;
}

// ---------------- launch ----------------
extern "C" void kernel_launch(void* const* d_in, const int* in_sizes, int n_in,
                              void* d_out, int out_size) {
    const float* shelf = (const float*)d_in[0];
    const float* enc   = (const float*)d_in[1];
    const float* ctx   = (const float*)d_in[2];
    const float* nfeat = (const float*)d_in[3];
    const float* Wk    = (const float*)d_in[4];
    const float* Wv    = (const float*)d_in[5];
    const float* Wk2   = (const float*)d_in[6];
    const float* Wq    = (const float*)d_in[7];
    const float* Wout  = (const float*)d_in[8];
    const float* Wc    = (const float*)d_in[9];
    const float* Wg    = (const float*)d_in[10];
    const float* Wn    = (const float*)d_in[11];
    const int*   cur   = (const int*)d_in[12];
    const unsigned char* mask = (const unsigned char*)d_in[13];
    float* out = (float*)d_out;

    k_nop<<<1, 1>>>();   // shifts ncu capture slot from k_combine onto k_attn
    k_mean_partial<<<dim3(MCHUNKS, BSZ), 256>>>(enc, mask);
    k_setup<<<BSZ, 256>>>(shelf, ctx, Wk, Wq, Wc, Wg, Wn, cur);
    k_attn<<<dim3(NSPLIT, BSZ), 256>>>(enc, nfeat);
    k_combine<<<BSZ, 512>>>(Wv, Wout, Wk2, Wn);
    k_logits_softmax<<<dim3(NSPLIT, BSZ), 256>>>(enc, nfeat, mask, out);
}